// round 2
// baseline (speedup 1.0000x reference)
#include <cuda_runtime.h>

#define N_NODES  50000
#define N_EDGES  800000
#define N_GRAPHS 256
#define DF       128
#define NHID     256
#define NOUT     768

// ---------------- scratch (device globals: no allocs allowed) ----------------
__device__ float g_h[N_NODES * DF];     // layer input/output features
__device__ float g_y[N_NODES * DF];     // dinv-scaled GEMM output (gather source)
__device__ int   g_deg[N_NODES];
__device__ int   g_rowptr[N_NODES + 1];
__device__ int   g_cur[N_NODES];
__device__ int   g_eidx[N_EDGES];       // CSR-by-dst: src node ids
__device__ float g_dinv[N_NODES];
__device__ float g_pool[N_GRAPHS * DF];
__device__ float g_cnt[N_GRAPHS];
__device__ float g_mlp[N_GRAPHS * NHID];
__device__ int   g_is64;                // 1 if indices are int64, 0 if int32

// dtype-agnostic index read: element i of an index array that is either
// int32[] or int64[] depending on g_is64 (detected at runtime).
__device__ __forceinline__ int idx_at(const void* p, long long i, int is64) {
    if (is64) return (int)((const long long*)p)[i];
    return ((const int*)p)[i];
}

// ---------------- dtype detection ----------------
// Interpret the first 512 elements as int64. Valid int64 edge data is always
// in [0, N_NODES). int32 data misread as int64 has a random high word -> out
// of range with overwhelming probability.
__global__ void k_detect(const void* ei) {
    if (threadIdx.x == 0) g_is64 = 1;
    __syncthreads();
    long long v = ((const long long*)ei)[threadIdx.x];  // 512 threads
    if (v < 0 || v >= N_NODES) atomicAnd(&g_is64, 0);
}

// ---------------- graph preprocessing ----------------
__global__ void k_zero() {
    int i = blockIdx.x * blockDim.x + threadIdx.x;
    if (i < N_NODES) g_deg[i] = 0;
    if (i < N_GRAPHS * DF) g_pool[i] = 0.f;
    if (i < N_GRAPHS) g_cnt[i] = 0.f;
}

__global__ void k_deg(const void* __restrict__ ei) {
    int e = blockIdx.x * blockDim.x + threadIdx.x;
    if (e < N_EDGES) {
        int d = idx_at(ei, (long long)N_EDGES + e, g_is64);   // dst row
        atomicAdd(&g_deg[d], 1);
    }
}

// single-block chunked inclusive scan -> exclusive rowptr
__global__ void k_scan() {
    __shared__ int s[1024];
    __shared__ int base;
    int tid = threadIdx.x;
    if (tid == 0) { base = 0; g_rowptr[0] = 0; }
    __syncthreads();
    for (int c0 = 0; c0 < N_NODES; c0 += 1024) {
        int i = c0 + tid;
        int v = (i < N_NODES) ? g_deg[i] : 0;
        s[tid] = v;
        __syncthreads();
        #pragma unroll
        for (int off = 1; off < 1024; off <<= 1) {
            int t = (tid >= off) ? s[tid - off] : 0;
            __syncthreads();
            s[tid] += t;
            __syncthreads();
        }
        if (i < N_NODES) g_rowptr[i + 1] = base + s[tid];
        __syncthreads();
        if (tid == 0) base += s[1023];
        __syncthreads();
    }
}

__global__ void k_prep() {
    int v = blockIdx.x * blockDim.x + threadIdx.x;
    if (v < N_NODES) {
        g_dinv[v] = rsqrtf((float)(g_deg[v] + 1));  // +1 self loop; always > 0
        g_cur[v]  = g_rowptr[v];
    }
}

__global__ void k_fill(const void* __restrict__ ei) {
    int e = blockIdx.x * blockDim.x + threadIdx.x;
    if (e < N_EDGES) {
        int is64 = g_is64;
        int s = idx_at(ei, e, is64);                         // src row
        int d = idx_at(ei, (long long)N_EDGES + e, is64);    // dst row
        int pos = atomicAdd(&g_cur[d], 1);
        g_eidx[pos] = s;
    }
}

// ---------------- GEMM: g_y[v,:] = (X @ W)[v,:] * dinv[v] ----------------
// X: [N_NODES,128], W: [128,128]. Tile 64 rows x 128 cols, 256 threads,
// each thread computes 8 rows x 4 cols.
__global__ void __launch_bounds__(256) k_gemm(const float* __restrict__ Xin,
                                              int use_internal,
                                              const float* __restrict__ W) {
    const float* X = use_internal ? g_h : Xin;
    __shared__ float Ws[64][128];
    __shared__ float Xs[64][64];   // [row][k]
    int tid = threadIdx.x;
    int row0 = blockIdx.x * 64;
    int c0 = (tid & 31) * 4;
    int r0 = (tid >> 5) * 8;
    float acc[8][4] = {};

    for (int kt = 0; kt < 128; kt += 64) {
        #pragma unroll
        for (int i = 0; i < 32; i++) {              // Ws: 64x128
            int idx = tid + i * 256;
            int k = idx >> 7, c = idx & 127;
            Ws[k][c] = W[(kt + k) * 128 + c];
        }
        #pragma unroll
        for (int i = 0; i < 16; i++) {              // Xs: 64 rows x 64 k
            int idx = tid + i * 256;
            int r = idx >> 6, k = idx & 63;
            int grow = row0 + r;
            Xs[r][k] = (grow < N_NODES) ? X[grow * 128 + kt + k] : 0.f;
        }
        __syncthreads();
        #pragma unroll
        for (int k = 0; k < 64; k++) {
            float4 w = *(const float4*)&Ws[k][c0];
            #pragma unroll
            for (int i = 0; i < 8; i++) {
                float xv = Xs[r0 + i][k];
                acc[i][0] += xv * w.x;
                acc[i][1] += xv * w.y;
                acc[i][2] += xv * w.z;
                acc[i][3] += xv * w.w;
            }
        }
        __syncthreads();
    }
    #pragma unroll
    for (int i = 0; i < 8; i++) {
        int grow = row0 + r0 + i;
        if (grow < N_NODES) {
            float dv = g_dinv[grow];
            float4 o = make_float4(acc[i][0] * dv, acc[i][1] * dv,
                                   acc[i][2] * dv, acc[i][3] * dv);
            *(float4*)&g_y[grow * 128 + c0] = o;
        }
    }
}

// ---------------- gather-sum per node (atomic-free message passing) ----------
// h[v,:] = act( dinv[v] * ( y'[v,:] + sum_{s->v} y'[s,:] ) + b )
__global__ void k_gather(const float* __restrict__ b, int relu) {
    int t = blockIdx.x * blockDim.x + threadIdx.x;
    int v = t >> 5;
    int lane = t & 31;
    if (v >= N_NODES) return;
    const float4* yp = (const float4*)g_y;
    float4 acc = yp[v * 32 + lane];                 // self loop
    int beg = g_rowptr[v], end = g_rowptr[v + 1];
    for (int e = beg; e < end; e++) {
        int s = g_eidx[e];
        float4 m = yp[s * 32 + lane];
        acc.x += m.x; acc.y += m.y; acc.z += m.z; acc.w += m.w;
    }
    float dv = g_dinv[v];
    float4 bb = ((const float4*)b)[lane];
    float4 o = make_float4(dv * acc.x + bb.x, dv * acc.y + bb.y,
                           dv * acc.z + bb.z, dv * acc.w + bb.w);
    if (relu) {
        o.x = fmaxf(o.x, 0.f); o.y = fmaxf(o.y, 0.f);
        o.z = fmaxf(o.z, 0.f); o.w = fmaxf(o.w, 0.f);
    }
    ((float4*)g_h)[v * 32 + lane] = o;
}

// ---------------- global mean pool (sums + counts) ----------------
__global__ void k_pool(const void* __restrict__ batch) {
    int t = blockIdx.x * blockDim.x + threadIdx.x;
    int v = t >> 5;
    int lane = t & 31;
    if (v >= N_NODES) return;
    int g = idx_at(batch, v, g_is64);
    float4 h = ((const float4*)g_h)[v * 32 + lane];
    float* p = &g_pool[g * DF + lane * 4];
    atomicAdd(p + 0, h.x);
    atomicAdd(p + 1, h.y);
    atomicAdd(p + 2, h.z);
    atomicAdd(p + 3, h.w);
    if (lane == 0) atomicAdd(&g_cnt[g], 1.f);
}

// ---------------- MLP head ----------------
__global__ void k_mlp1(const float* __restrict__ Wm1, const float* __restrict__ bm1) {
    __shared__ float p[DF];
    int g = blockIdx.x;
    int j = threadIdx.x;                 // 256 threads
    float inv = 1.f / fmaxf(g_cnt[g], 1.f);
    if (j < DF) p[j] = g_pool[g * DF + j] * inv;
    __syncthreads();
    float acc = bm1[j];
    #pragma unroll
    for (int k = 0; k < DF; k++) acc += p[k] * Wm1[k * NHID + j];
    g_mlp[g * NHID + j] = fmaxf(acc, 0.f);
}

__global__ void k_mlp2(const float* __restrict__ Wm2, const float* __restrict__ bm2,
                       float* __restrict__ out) {
    __shared__ float p[NHID];
    int g = blockIdx.x;
    int j = threadIdx.x;                 // 768 threads
    if (j < NHID) p[j] = g_mlp[g * NHID + j];
    __syncthreads();
    float acc = bm2[j];
    #pragma unroll 8
    for (int k = 0; k < NHID; k++) acc += p[k] * Wm2[k * NOUT + j];
    out[g * NOUT + j] = acc;
}

// ---------------- launch ----------------
extern "C" void kernel_launch(void* const* d_in, const int* in_sizes, int n_in,
                              void* d_out, int out_size) {
    const float* x     = (const float*)d_in[0];
    const void*  ei    = d_in[1];        // int32 or int64, detected on device
    const void*  batch = d_in[2];
    const float* W1  = (const float*)d_in[3];
    const float* b1  = (const float*)d_in[4];
    const float* W2  = (const float*)d_in[5];
    const float* b2  = (const float*)d_in[6];
    const float* W3  = (const float*)d_in[7];
    const float* b3  = (const float*)d_in[8];
    const float* Wm1 = (const float*)d_in[9];
    const float* bm1 = (const float*)d_in[10];
    const float* Wm2 = (const float*)d_in[11];
    const float* bm2 = (const float*)d_in[12];
    float* out = (float*)d_out;

    const int ZB = (N_NODES + 255) / 256;
    const int EB = (N_EDGES + 255) / 256;
    const int GB = (N_NODES + 63) / 64;          // gemm row tiles
    const int WB = (N_NODES * 32 + 255) / 256;   // warp-per-node kernels

    // dtype detect + CSR build + norms
    k_detect<<<1, 512>>>(ei);
    k_zero<<<ZB, 256>>>();
    k_deg <<<EB, 256>>>(ei);
    k_scan<<<1, 1024>>>();
    k_prep<<<ZB, 256>>>();
    k_fill<<<EB, 256>>>(ei);

    // layer 1
    k_gemm  <<<GB, 256>>>(x, 0, W1);
    k_gather<<<WB, 256>>>(b1, 1);
    // layer 2
    k_gemm  <<<GB, 256>>>(nullptr, 1, W2);
    k_gather<<<WB, 256>>>(b2, 1);
    // layer 3 (no relu)
    k_gemm  <<<GB, 256>>>(nullptr, 1, W3);
    k_gather<<<WB, 256>>>(b3, 0);

    // pooling + MLP head
    k_pool<<<WB, 256>>>(batch);
    k_mlp1<<<N_GRAPHS, NHID>>>(Wm1, bm1);
    k_mlp2<<<N_GRAPHS, NOUT>>>(Wm2, bm2, out);
}

// round 3
// speedup vs baseline: 1.3616x; 1.3616x over previous
#include <cuda_runtime.h>

#define N_NODES  50000
#define N_EDGES  800000
#define N_GRAPHS 256
#define DF       128
#define NHID     256
#define NOUT     768
#define SCAN_B   ((N_NODES + 1023) / 1024)

// ---------------- scratch (device globals: no allocs allowed) ----------------
__device__ float g_h[N_NODES * DF];     // layer input/output features
__device__ float g_y[N_NODES * DF];     // dinv-scaled GEMM output (gather source)
__device__ int   g_deg[N_NODES];
__device__ int   g_rowptr[N_NODES + 1];
__device__ int   g_cur[N_NODES];
__device__ int   g_eidx[N_EDGES];       // CSR-by-dst: src node ids
__device__ float g_dinv[N_NODES];
__device__ float g_pool[N_GRAPHS * DF];
__device__ float g_mlp[N_GRAPHS * NHID];
__device__ int   g_part[64];
__device__ int   g_part2[64];
__device__ int   g_is64;                // 1 if indices are int64, 0 if int32

__device__ __forceinline__ int idx_at(const void* p, long long i, int is64) {
    if (is64) return (int)((const long long*)p)[i];
    return ((const int*)p)[i];
}

// ---------------- dtype detection ----------------
__global__ void k_detect(const void* ei) {
    if (threadIdx.x == 0) g_is64 = 1;
    __syncthreads();
    long long v = ((const long long*)ei)[threadIdx.x];  // 512 threads
    if (v < 0 || v >= N_NODES) atomicAnd(&g_is64, 0);
}

// ---------------- graph preprocessing ----------------
__global__ void k_zero() {
    int i = blockIdx.x * blockDim.x + threadIdx.x;
    if (i < N_NODES) g_deg[i] = 0;
}

__global__ void k_deg(const void* __restrict__ ei) {
    int e = blockIdx.x * blockDim.x + threadIdx.x;
    if (e < N_EDGES) {
        int d = idx_at(ei, (long long)N_EDGES + e, g_is64);   // dst row
        atomicAdd(&g_deg[d], 1);
    }
}

// phase 1: per-block inclusive scan; write intra prefix + block sum
__global__ void k_scan1() {
    __shared__ int s[1024];
    int tid = threadIdx.x;
    int i = blockIdx.x * 1024 + tid;
    s[tid] = (i < N_NODES) ? g_deg[i] : 0;
    __syncthreads();
    #pragma unroll
    for (int off = 1; off < 1024; off <<= 1) {
        int t = (tid >= off) ? s[tid - off] : 0;
        __syncthreads();
        s[tid] += t;
        __syncthreads();
    }
    if (i < N_NODES) g_rowptr[i + 1] = s[tid];
    if (tid == 1023) g_part[blockIdx.x] = s[1023];
}

// phase 2: exclusive scan of block partials (tiny)
__global__ void k_scan2() {
    if (threadIdx.x == 0) {
        int a = 0;
        for (int b = 0; b < SCAN_B; b++) { g_part2[b] = a; a += g_part[b]; }
    }
}

// phase 3: add block offsets
__global__ void k_scan3() {
    int i = blockIdx.x * blockDim.x + threadIdx.x;
    if (i == 0) g_rowptr[0] = 0;
    if (i < N_NODES) g_rowptr[i + 1] += g_part2[i >> 10];
}

__global__ void k_prep() {
    int v = blockIdx.x * blockDim.x + threadIdx.x;
    if (v < N_NODES) {
        g_dinv[v] = rsqrtf((float)(g_deg[v] + 1));  // +1 self loop; always > 0
        g_cur[v]  = g_rowptr[v];
    }
}

__global__ void k_fill(const void* __restrict__ ei) {
    int e = blockIdx.x * blockDim.x + threadIdx.x;
    if (e < N_EDGES) {
        int is64 = g_is64;
        int s = idx_at(ei, e, is64);                         // src
        int d = idx_at(ei, (long long)N_EDGES + e, is64);    // dst
        int pos = atomicAdd(&g_cur[d], 1);
        g_eidx[pos] = s;
    }
}

// ---------------- tensor-core GEMM (tf32 mma.sync) ----------------
// g_y[v,:] = (X @ W)[v,:] * dinv[v].  X:[N,128], W:[128,128].
// Block tile 128(M) x 128(N), K chunked by 32. 8 warps in 4x2, warp tile 32x64.
#define BK   32
#define PADA 36
#define PADB 136

__device__ __forceinline__ unsigned f2tf(float x) {
    unsigned u;
    asm("cvt.rna.tf32.f32 %0, %1;" : "=r"(u) : "f"(x));
    return u;
}

__device__ __forceinline__ void mma_tf32(float* d,
                                         const unsigned* a, const unsigned* b,
                                         const float* c) {
    asm volatile(
        "mma.sync.aligned.m16n8k8.row.col.f32.tf32.tf32.f32 "
        "{%0,%1,%2,%3}, {%4,%5,%6,%7}, {%8,%9}, {%10,%11,%12,%13};\n"
        : "=f"(d[0]), "=f"(d[1]), "=f"(d[2]), "=f"(d[3])
        : "r"(a[0]), "r"(a[1]), "r"(a[2]), "r"(a[3]),
          "r"(b[0]), "r"(b[1]),
          "f"(c[0]), "f"(c[1]), "f"(c[2]), "f"(c[3]));
}

__global__ void __launch_bounds__(256) k_gemm_tc(const float* __restrict__ Xin,
                                                 int use_internal,
                                                 const float* __restrict__ W) {
    const float* X = use_internal ? g_h : Xin;
    __shared__ float As[128 * PADA];
    __shared__ float Bs[BK * PADB];
    int tid  = threadIdx.x;
    int wid  = tid >> 5, lane = tid & 31;
    int wm   = wid >> 1, wn = wid & 1;       // 4 x 2 warps
    int grp  = lane >> 2, tig = lane & 3;
    int row0 = blockIdx.x * 128;

    float acc[2][8][4] = {};

    for (int kt = 0; kt < 128; kt += BK) {
        // cooperative load A tile: 128 x 32 (float4 per thread x4)
        #pragma unroll
        for (int i = 0; i < 4; i++) {
            int linear = (tid + i * 256) * 4;
            int r = linear >> 5, c = linear & 31;
            int grow = row0 + r;
            float4 v = (grow < N_NODES)
                         ? *(const float4*)&X[grow * 128 + kt + c]
                         : make_float4(0.f, 0.f, 0.f, 0.f);
            *(float4*)&As[r * PADA + c] = v;
        }
        // cooperative load B tile: 32 x 128
        #pragma unroll
        for (int i = 0; i < 4; i++) {
            int linear = (tid + i * 256) * 4;
            int k = linear >> 7, n = linear & 127;
            float4 v = *(const float4*)&W[(kt + k) * 128 + n];
            *(float4*)&Bs[k * PADB + n] = v;
        }
        __syncthreads();

        #pragma unroll
        for (int ka = 0; ka < 4; ka++) {
            int kb = ka * 8;
            unsigned a[2][4], b[8][2];
            #pragma unroll
            for (int m = 0; m < 2; m++) {
                int r = wm * 32 + m * 16 + grp;
                a[m][0] = f2tf(As[r * PADA + kb + tig]);
                a[m][1] = f2tf(As[(r + 8) * PADA + kb + tig]);
                a[m][2] = f2tf(As[r * PADA + kb + tig + 4]);
                a[m][3] = f2tf(As[(r + 8) * PADA + kb + tig + 4]);
            }
            #pragma unroll
            for (int n = 0; n < 8; n++) {
                int cn = wn * 64 + n * 8 + grp;
                b[n][0] = f2tf(Bs[(kb + tig) * PADB + cn]);
                b[n][1] = f2tf(Bs[(kb + tig + 4) * PADB + cn]);
            }
            #pragma unroll
            for (int m = 0; m < 2; m++)
                #pragma unroll
                for (int n = 0; n < 8; n++)
                    mma_tf32(acc[m][n], a[m], b[n], acc[m][n]);
        }
        __syncthreads();
    }

    // epilogue: scale by dinv, float2 stores
    #pragma unroll
    for (int m = 0; m < 2; m++) {
        #pragma unroll
        for (int half = 0; half < 2; half++) {
            int row = row0 + wm * 32 + m * 16 + grp + half * 8;
            if (row < N_NODES) {
                float dv = g_dinv[row];
                #pragma unroll
                for (int n = 0; n < 8; n++) {
                    int col = wn * 64 + n * 8 + 2 * tig;
                    float2 o = make_float2(acc[m][n][half * 2] * dv,
                                           acc[m][n][half * 2 + 1] * dv);
                    *(float2*)&g_y[row * 128 + col] = o;
                }
            }
        }
    }
}

// ---------------- gather-sum per node (atomic-free message passing) ----------
__global__ void k_gather(const float* __restrict__ b, int relu) {
    int t = blockIdx.x * blockDim.x + threadIdx.x;
    int v = t >> 5;
    int lane = t & 31;
    if (v >= N_NODES) return;
    const float4* yp = (const float4*)g_y;
    float4 acc = yp[v * 32 + lane];                 // self loop
    int beg = g_rowptr[v], end = g_rowptr[v + 1];
    for (int e = beg; e < end; e++) {
        int s = g_eidx[e];
        float4 m = yp[s * 32 + lane];
        acc.x += m.x; acc.y += m.y; acc.z += m.z; acc.w += m.w;
    }
    float dv = g_dinv[v];
    float4 bb = ((const float4*)b)[lane];
    float4 o = make_float4(dv * acc.x + bb.x, dv * acc.y + bb.y,
                           dv * acc.z + bb.z, dv * acc.w + bb.w);
    if (relu) {
        o.x = fmaxf(o.x, 0.f); o.y = fmaxf(o.y, 0.f);
        o.z = fmaxf(o.z, 0.f); o.w = fmaxf(o.w, 0.f);
    }
    ((float4*)g_h)[v * 32 + lane] = o;
}

// ---------------- global mean pool: one block per graph, batch is sorted -----
__global__ void k_poolg(const void* __restrict__ batch) {
    int g = blockIdx.x;
    int j = threadIdx.x;     // 128 threads = feature dims
    int is64 = g_is64;
    // lower bound
    int lo = 0, hi = N_NODES;
    while (lo < hi) { int m = (lo + hi) >> 1; if (idx_at(batch, m, is64) < g) lo = m + 1; else hi = m; }
    int beg = lo;
    // upper bound
    lo = 0; hi = N_NODES;
    while (lo < hi) { int m = (lo + hi) >> 1; if (idx_at(batch, m, is64) <= g) lo = m + 1; else hi = m; }
    int end = lo;
    float acc = 0.f;
    for (int v = beg; v < end; v++) acc += g_h[v * DF + j];
    float inv = (end > beg) ? 1.f / (float)(end - beg) : 0.f;
    g_pool[g * DF + j] = acc * inv;
}

// ---------------- MLP head ----------------
__global__ void k_mlp1(const float* __restrict__ Wm1, const float* __restrict__ bm1) {
    __shared__ float p[DF];
    int g = blockIdx.x;
    int j = threadIdx.x;                 // 256 threads
    if (j < DF) p[j] = g_pool[g * DF + j];
    __syncthreads();
    float acc = bm1[j];
    #pragma unroll
    for (int k = 0; k < DF; k++) acc += p[k] * Wm1[k * NHID + j];
    g_mlp[g * NHID + j] = fmaxf(acc, 0.f);
}

__global__ void k_mlp2(const float* __restrict__ Wm2, const float* __restrict__ bm2,
                       float* __restrict__ out) {
    __shared__ float p[NHID];
    int g = blockIdx.x;
    int j = threadIdx.x;                 // 768 threads
    if (j < NHID) p[j] = g_mlp[g * NHID + j];
    __syncthreads();
    float acc = bm2[j];
    #pragma unroll 8
    for (int k = 0; k < NHID; k++) acc += p[k] * Wm2[k * NOUT + j];
    out[g * NOUT + j] = acc;
}

// ---------------- launch ----------------
extern "C" void kernel_launch(void* const* d_in, const int* in_sizes, int n_in,
                              void* d_out, int out_size) {
    const float* x     = (const float*)d_in[0];
    const void*  ei    = d_in[1];        // int32 or int64, detected on device
    const void*  batch = d_in[2];
    const float* W1  = (const float*)d_in[3];
    const float* b1  = (const float*)d_in[4];
    const float* W2  = (const float*)d_in[5];
    const float* b2  = (const float*)d_in[6];
    const float* W3  = (const float*)d_in[7];
    const float* b3  = (const float*)d_in[8];
    const float* Wm1 = (const float*)d_in[9];
    const float* bm1 = (const float*)d_in[10];
    const float* Wm2 = (const float*)d_in[11];
    const float* bm2 = (const float*)d_in[12];
    float* out = (float*)d_out;

    const int ZB = (N_NODES + 255) / 256;
    const int EB = (N_EDGES + 255) / 256;
    const int GB = (N_NODES + 127) / 128;        // gemm row tiles
    const int WB = (N_NODES * 32 + 255) / 256;   // warp-per-node kernels

    // dtype detect + CSR build + norms
    k_detect<<<1, 512>>>(ei);
    k_zero <<<ZB, 256>>>();
    k_deg  <<<EB, 256>>>(ei);
    k_scan1<<<SCAN_B, 1024>>>();
    k_scan2<<<1, 32>>>();
    k_scan3<<<ZB, 256>>>();
    k_prep <<<ZB, 256>>>();
    k_fill <<<EB, 256>>>(ei);

    // layer 1
    k_gemm_tc<<<GB, 256>>>(x, 0, W1);
    k_gather <<<WB, 256>>>(b1, 1);
    // layer 2
    k_gemm_tc<<<GB, 256>>>(nullptr, 1, W2);
    k_gather <<<WB, 256>>>(b2, 1);
    // layer 3 (no relu)
    k_gemm_tc<<<GB, 256>>>(nullptr, 1, W3);
    k_gather <<<WB, 256>>>(b3, 0);

    // pooling + MLP head
    k_poolg<<<N_GRAPHS, DF>>>(batch);
    k_mlp1 <<<N_GRAPHS, NHID>>>(Wm1, bm1);
    k_mlp2 <<<N_GRAPHS, NOUT>>>(Wm2, bm2, out);
}

// round 6
// speedup vs baseline: 1.9307x; 1.4179x over previous
#include <cuda_runtime.h>
#include <cuda_fp16.h>

#define N_NODES  50000
#define N_EDGES  800000
#define N_GRAPHS 256
#define DF       128
#define NHID     256
#define NOUT     768
#define SCAN_B   ((N_NODES + 1023) / 1024)

// ---------------- scratch (device globals: no allocs allowed) ----------------
__device__ float g_h[N_NODES * DF];       // layer features (fp32, GEMM input)
__device__ uint2 g_y16[N_NODES * DF / 4]; // dinv-scaled GEMM out, fp16 (gather src)
__device__ int   g_deg[N_NODES];
__device__ int   g_rowptr[N_NODES + 1];
__device__ int   g_cur[N_NODES];
__device__ int   g_eidx[N_EDGES];         // CSR-by-dst: src node ids
__device__ float g_dinv[N_NODES];
__device__ float g_pool[N_GRAPHS * DF];
__device__ float g_mlp[N_GRAPHS * NHID];
__device__ int   g_part[64];
__device__ int   g_part2[64];
__device__ int   g_is64;                  // 1 if indices are int64, 0 if int32

__device__ __forceinline__ int idx_at(const void* p, long long i, int is64) {
    if (is64) return (int)((const long long*)p)[i];
    return ((const int*)p)[i];
}

// ---------------- dtype detection ----------------
__global__ void k_detect(const void* ei) {
    if (threadIdx.x == 0) g_is64 = 1;
    __syncthreads();
    long long v = ((const long long*)ei)[threadIdx.x];  // 512 threads
    if (v < 0 || v >= N_NODES) atomicAnd(&g_is64, 0);
}

// ---------------- graph preprocessing ----------------
__global__ void k_zero() {
    int i = blockIdx.x * blockDim.x + threadIdx.x;
    if (i < N_NODES) g_deg[i] = 0;
}

__global__ void k_deg(const void* __restrict__ ei) {
    int e = blockIdx.x * blockDim.x + threadIdx.x;
    if (e < N_EDGES) {
        int d = idx_at(ei, (long long)N_EDGES + e, g_is64);   // dst row
        atomicAdd(&g_deg[d], 1);
    }
}

__global__ void k_scan1() {
    __shared__ int s[1024];
    int tid = threadIdx.x;
    int i = blockIdx.x * 1024 + tid;
    s[tid] = (i < N_NODES) ? g_deg[i] : 0;
    __syncthreads();
    #pragma unroll
    for (int off = 1; off < 1024; off <<= 1) {
        int t = (tid >= off) ? s[tid - off] : 0;
        __syncthreads();
        s[tid] += t;
        __syncthreads();
    }
    if (i < N_NODES) g_rowptr[i + 1] = s[tid];
    if (tid == 1023) g_part[blockIdx.x] = s[1023];
}

__global__ void k_scan2() {
    if (threadIdx.x == 0) {
        int a = 0;
        for (int b = 0; b < SCAN_B; b++) { g_part2[b] = a; a += g_part[b]; }
    }
}

__global__ void k_scan3() {
    int i = blockIdx.x * blockDim.x + threadIdx.x;
    if (i == 0) g_rowptr[0] = 0;
    if (i < N_NODES) g_rowptr[i + 1] += g_part2[i >> 10];
}

__global__ void k_prep() {
    int v = blockIdx.x * blockDim.x + threadIdx.x;
    if (v < N_NODES) {
        g_dinv[v] = rsqrtf((float)(g_deg[v] + 1));  // +1 self loop; always > 0
        g_cur[v]  = g_rowptr[v];
    }
}

__global__ void k_fill(const void* __restrict__ ei) {
    int e = blockIdx.x * blockDim.x + threadIdx.x;
    if (e < N_EDGES) {
        int is64 = g_is64;
        int s = idx_at(ei, e, is64);                         // src
        int d = idx_at(ei, (long long)N_EDGES + e, is64);    // dst
        int pos = atomicAdd(&g_cur[d], 1);
        g_eidx[pos] = s;
    }
}

// ---------------- tensor-core GEMM (tf32 mma.sync) ----------------
// y16[v,:] = fp16( (X @ W)[v,:] * dinv[v] ).  X:[N,128] fp32, W:[128,128] fp32.
// Block tile 128(M) x 128(N), K chunked by 32. 8 warps 4x2, warp tile 32x64.
// tf32 conversion happens ONCE at smem-store time.
#define BK   32
#define PADA 36
#define PADB 136

__device__ __forceinline__ unsigned f2tf(float x) {
    unsigned u;
    asm("cvt.rna.tf32.f32 %0, %1;" : "=r"(u) : "f"(x));
    return u;
}

__device__ __forceinline__ void mma_tf32(float* d,
                                         const unsigned* a, const unsigned* b,
                                         const float* c) {
    asm volatile(
        "mma.sync.aligned.m16n8k8.row.col.f32.tf32.tf32.f32 "
        "{%0,%1,%2,%3}, {%4,%5,%6,%7}, {%8,%9}, {%10,%11,%12,%13};\n"
        : "=f"(d[0]), "=f"(d[1]), "=f"(d[2]), "=f"(d[3])
        : "r"(a[0]), "r"(a[1]), "r"(a[2]), "r"(a[3]),
          "r"(b[0]), "r"(b[1]),
          "f"(c[0]), "f"(c[1]), "f"(c[2]), "f"(c[3]));
}

__global__ void __launch_bounds__(256) k_gemm_tc(const float* __restrict__ Xin,
                                                 int use_internal,
                                                 const float* __restrict__ W) {
    const float* X = use_internal ? g_h : Xin;
    __shared__ unsigned As[128 * PADA];
    __shared__ unsigned Bs[BK * PADB];
    int tid  = threadIdx.x;
    int wid  = tid >> 5, lane = tid & 31;
    int wm   = wid >> 1, wn = wid & 1;       // 4 x 2 warps
    int grp  = lane >> 2, tig = lane & 3;
    int row0 = blockIdx.x * 128;

    float acc[2][8][4] = {};

    for (int kt = 0; kt < 128; kt += BK) {
        #pragma unroll
        for (int i = 0; i < 4; i++) {        // A tile 128x32
            int linear = (tid + i * 256) * 4;
            int r = linear >> 5, c = linear & 31;
            int grow = row0 + r;
            float4 v = (grow < N_NODES)
                         ? *(const float4*)&X[grow * 128 + kt + c]
                         : make_float4(0.f, 0.f, 0.f, 0.f);
            uint4 u = make_uint4(f2tf(v.x), f2tf(v.y), f2tf(v.z), f2tf(v.w));
            *(uint4*)&As[r * PADA + c] = u;
        }
        #pragma unroll
        for (int i = 0; i < 4; i++) {        // B tile 32x128
            int linear = (tid + i * 256) * 4;
            int k = linear >> 7, n = linear & 127;
            float4 v = *(const float4*)&W[(kt + k) * 128 + n];
            uint4 u = make_uint4(f2tf(v.x), f2tf(v.y), f2tf(v.z), f2tf(v.w));
            *(uint4*)&Bs[k * PADB + n] = u;
        }
        __syncthreads();

        #pragma unroll
        for (int ka = 0; ka < 4; ka++) {
            int kb = ka * 8;
            unsigned a[2][4], b[8][2];
            #pragma unroll
            for (int m = 0; m < 2; m++) {
                int r = wm * 32 + m * 16 + grp;
                a[m][0] = As[r * PADA + kb + tig];
                a[m][1] = As[(r + 8) * PADA + kb + tig];
                a[m][2] = As[r * PADA + kb + tig + 4];
                a[m][3] = As[(r + 8) * PADA + kb + tig + 4];
            }
            #pragma unroll
            for (int n = 0; n < 8; n++) {
                int cn = wn * 64 + n * 8 + grp;
                b[n][0] = Bs[(kb + tig) * PADB + cn];
                b[n][1] = Bs[(kb + tig + 4) * PADB + cn];
            }
            #pragma unroll
            for (int m = 0; m < 2; m++)
                #pragma unroll
                for (int n = 0; n < 8; n++)
                    mma_tf32(acc[m][n], a[m], b[n], acc[m][n]);
        }
        __syncthreads();
    }

    // epilogue: scale by dinv, convert to fp16, half2 stores
    __half2* yp = (__half2*)g_y16;
    #pragma unroll
    for (int m = 0; m < 2; m++) {
        #pragma unroll
        for (int half = 0; half < 2; half++) {
            int row = row0 + wm * 32 + m * 16 + grp + half * 8;
            if (row < N_NODES) {
                float dv = g_dinv[row];
                #pragma unroll
                for (int n = 0; n < 8; n++) {
                    int col = wn * 64 + n * 8 + 2 * tig;
                    yp[row * 64 + (col >> 1)] =
                        __floats2half2_rn(acc[m][n][half * 2] * dv,
                                          acc[m][n][half * 2 + 1] * dv);
                }
            }
        }
    }
}

// ---------------- gather-sum per node (fp16 messages, fp32 accumulate) -------
// h[v,:] = act( dinv[v] * ( y'[v,:] + sum_{s->v} y'[s,:] ) + b )
__device__ __forceinline__ void acc_row(float4& a, uint2 raw) {
    float2 lo = __half22float2(*(__half2*)&raw.x);
    float2 hi = __half22float2(*(__half2*)&raw.y);
    a.x += lo.x; a.y += lo.y; a.z += hi.x; a.w += hi.y;
}

__global__ void k_gather(const float* __restrict__ b, int relu) {
    int t = blockIdx.x * blockDim.x + threadIdx.x;
    int v = t >> 5;
    int lane = t & 31;
    if (v >= N_NODES) return;
    float4 acc = make_float4(0.f, 0.f, 0.f, 0.f);
    acc_row(acc, g_y16[v * 32 + lane]);             // self loop
    int e = g_rowptr[v], end = g_rowptr[v + 1];
    for (; e + 1 < end; e += 2) {                   // 2-way unroll for MLP
        int s0 = g_eidx[e], s1 = g_eidx[e + 1];
        uint2 r0 = g_y16[s0 * 32 + lane];
        uint2 r1 = g_y16[s1 * 32 + lane];
        acc_row(acc, r0);
        acc_row(acc, r1);
    }
    if (e < end) acc_row(acc, g_y16[g_eidx[e] * 32 + lane]);

    float dv = g_dinv[v];
    float4 bb = ((const float4*)b)[lane];
    float4 o = make_float4(dv * acc.x + bb.x, dv * acc.y + bb.y,
                           dv * acc.z + bb.z, dv * acc.w + bb.w);
    if (relu) {
        o.x = fmaxf(o.x, 0.f); o.y = fmaxf(o.y, 0.f);
        o.z = fmaxf(o.z, 0.f); o.w = fmaxf(o.w, 0.f);
    }
    ((float4*)g_h)[v * 32 + lane] = o;
}

// ---------------- global mean pool: one block per graph, batch is sorted -----
__global__ void k_poolg(const void* __restrict__ batch) {
    int g = blockIdx.x;
    int j = threadIdx.x;     // 128 threads = feature dims
    int is64 = g_is64;
    int lo = 0, hi = N_NODES;
    while (lo < hi) { int m = (lo + hi) >> 1; if (idx_at(batch, m, is64) < g) lo = m + 1; else hi = m; }
    int beg = lo;
    lo = 0; hi = N_NODES;
    while (lo < hi) { int m = (lo + hi) >> 1; if (idx_at(batch, m, is64) <= g) lo = m + 1; else hi = m; }
    int end = lo;
    float acc = 0.f;
    for (int v = beg; v < end; v++) acc += g_h[v * DF + j];
    float inv = (end > beg) ? 1.f / (float)(end - beg) : 0.f;
    g_pool[g * DF + j] = acc * inv;
}

// ---------------- MLP head (4 graphs per block for weight reuse) -------------
__global__ void k_mlp1(const float* __restrict__ Wm1, const float* __restrict__ bm1) {
    __shared__ float p[4][DF];
    int g0 = blockIdx.x * 4;
    int j = threadIdx.x;                 // 256 threads
    #pragma unroll
    for (int i = j; i < 4 * DF; i += NHID) p[i >> 7][i & 127] = g_pool[g0 * DF + i];
    __syncthreads();
    float bias = bm1[j];
    float a0 = bias, a1 = bias, a2 = bias, a3 = bias;
    #pragma unroll 4
    for (int k = 0; k < DF; k++) {
        float w = Wm1[k * NHID + j];
        a0 += p[0][k] * w; a1 += p[1][k] * w;
        a2 += p[2][k] * w; a3 += p[3][k] * w;
    }
    g_mlp[(g0 + 0) * NHID + j] = fmaxf(a0, 0.f);
    g_mlp[(g0 + 1) * NHID + j] = fmaxf(a1, 0.f);
    g_mlp[(g0 + 2) * NHID + j] = fmaxf(a2, 0.f);
    g_mlp[(g0 + 3) * NHID + j] = fmaxf(a3, 0.f);
}

__global__ void k_mlp2(const float* __restrict__ Wm2, const float* __restrict__ bm2,
                       float* __restrict__ out) {
    __shared__ float p[4][NHID];
    int g0 = blockIdx.x * 4;
    int j = threadIdx.x;                 // 768 threads
    for (int i = j; i < 4 * NHID; i += NOUT) p[i >> 8][i & 255] = g_mlp[g0 * NHID + i];
    __syncthreads();
    float bias = bm2[j];
    float a0 = bias, a1 = bias, a2 = bias, a3 = bias;
    #pragma unroll 4
    for (int k = 0; k < NHID; k++) {
        float w = Wm2[k * NOUT + j];
        a0 += p[0][k] * w; a1 += p[1][k] * w;
        a2 += p[2][k] * w; a3 += p[3][k] * w;
    }
    out[(g0 + 0) * NOUT + j] = a0;
    out[(g0 + 1) * NOUT + j] = a1;
    out[(g0 + 2) * NOUT + j] = a2;
    out[(g0 + 3) * NOUT + j] = a3;
}

// ---------------- launch ----------------
extern "C" void kernel_launch(void* const* d_in, const int* in_sizes, int n_in,
                              void* d_out, int out_size) {
    const float* x     = (const float*)d_in[0];
    const void*  ei    = d_in[1];        // int32 or int64, detected on device
    const void*  batch = d_in[2];
    const float* W1  = (const float*)d_in[3];
    const float* b1  = (const float*)d_in[4];
    const float* W2  = (const float*)d_in[5];
    const float* b2  = (const float*)d_in[6];
    const float* W3  = (const float*)d_in[7];
    const float* b3  = (const float*)d_in[8];
    const float* Wm1 = (const float*)d_in[9];
    const float* bm1 = (const float*)d_in[10];
    const float* Wm2 = (const float*)d_in[11];
    const float* bm2 = (const float*)d_in[12];
    float* out = (float*)d_out;

    const int ZB = (N_NODES + 255) / 256;
    const int EB = (N_EDGES + 255) / 256;
    const int GB = (N_NODES + 127) / 128;        // gemm row tiles
    const int WB = (N_NODES * 32 + 255) / 256;   // warp-per-node kernels

    // dtype detect + CSR build + norms
    k_detect<<<1, 512>>>(ei);
    k_zero <<<ZB, 256>>>();
    k_deg  <<<EB, 256>>>(ei);
    k_scan1<<<SCAN_B, 1024>>>();
    k_scan2<<<1, 32>>>();
    k_scan3<<<ZB, 256>>>();
    k_prep <<<ZB, 256>>>();
    k_fill <<<EB, 256>>>(ei);

    // layer 1
    k_gemm_tc<<<GB, 256>>>(x, 0, W1);
    k_gather <<<WB, 256>>>(b1, 1);
    // layer 2
    k_gemm_tc<<<GB, 256>>>(nullptr, 1, W2);
    k_gather <<<WB, 256>>>(b2, 1);
    // layer 3 (no relu)
    k_gemm_tc<<<GB, 256>>>(nullptr, 1, W3);
    k_gather <<<WB, 256>>>(b3, 0);

    // pooling + MLP head
    k_poolg<<<N_GRAPHS, DF>>>(batch);
    k_mlp1 <<<N_GRAPHS / 4, NHID>>>(Wm1, bm1);
    k_mlp2 <<<N_GRAPHS / 4, NOUT>>>(Wm2, bm2, out);
}